// round 13
// baseline (speedup 1.0000x reference)
#include <cuda_runtime.h>

#define BATCH  4096
#define TSTEPS 100
#define DDIM   100
#define OOUT   3
#define CW     (BATCH * OOUT)

#define FPSCALE 67108864.0f                       /* 2^26 */
#define INV_FPSCALE 1.490116119384765625e-8f      /* 2^-26 */

#define ROUNDS 25   /* 4 timesteps (rows) per round */

// Two warps per batch element (T-split). Per round of 4 rows:
//   warp A computes int dot-sums (mask->LUT->REDUX) for rows 4p,4p+1
//   warp B for rows 4p+2,4p+3; both deposit to double-buffered smem;
//   named-barrier(64); warp A scans 4 leaky steps and stores.
// Int sums identical to the 1-warp version -> bit-identical outputs.
__global__ __launch_bounds__(128, 12) void leaky_fused(
    const float* __restrict__ x, const float* __restrict__ u,
    const float* __restrict__ W, const float* __restrict__ bias,
    const float* __restrict__ betap, const float* __restrict__ thrp,
    float* __restrict__ out)
{
    __shared__ int4 lut[16 * 32];          // 2 KB
    __shared__ int  sums[2][2][4][3];      // [batchInBlk][slot][row][chan]

    // LUT[mask][lane] = fixed-point subset sums of lane's 4 weight columns
    for (int e = threadIdx.x; e < 16 * 32; e += 128) {
        const int mask = e >> 5;
        const int ln   = e & 31;
        int s0 = 0, s1 = 0, s2 = 0;
        if (ln < (DDIM / 4)) {
            #pragma unroll
            for (int bit = 0; bit < 4; ++bit) {
                if ((mask >> bit) & 1) {
                    const int col = ln * 4 + bit;
                    s0 += __float2int_rn(__ldg(W + 0 * DDIM + col) * FPSCALE);
                    s1 += __float2int_rn(__ldg(W + 1 * DDIM + col) * FPSCALE);
                    s2 += __float2int_rn(__ldg(W + 2 * DDIM + col) * FPSCALE);
                }
            }
        }
        lut[(mask << 5) | ln] = make_int4(s0, s1, s2, 0);
    }
    __syncthreads();

    const int wid    = threadIdx.x >> 5;        // 0..3
    const int pairid = wid >> 1;                // 0..1 (batch within block)
    const int isB    = wid & 1;                 // 0 = scan warp, 1 = helper
    const int lane   = threadIdx.x & 31;
    const int gw     = (blockIdx.x << 1) | pairid;   // batch id (grid exact)
    const bool act   = (lane < (DDIM / 4));     // 25 active load lanes

    const float beta = __ldg(betap);
    const float thr  = __ldg(thrp);
    const float bl   = __ldg(bias + ((lane < 2) ? lane : 2));

    const float4 z = make_float4(0.f, 0.f, 0.f, 0.f);
    const float4* __restrict__ xr = (const float4*)(x + (size_t)gw * (TSTEPS * DDIM));
    const float4* __restrict__ ur = (const float4*)(u + (size_t)gw * (TSTEPS * DDIM));

    float* __restrict__ spk = out;
    float* __restrict__ mem = out + (size_t)TSTEPS * CW;

    const int rowoff = isB * 2;   // rows 4p+rowoff, 4p+rowoff+1

    // load this warp's round-0 pair
    float4 cx0 = z, cu0 = z, cx1 = z, cu1 = z;
    if (act) {
        const int base = rowoff * (DDIM / 4) + lane;
        cx0 = xr[base];              cu0 = ur[base];
        cx1 = xr[base + (DDIM / 4)]; cu1 = ur[base + (DDIM / 4)];
    }

    float m = 0.f;   // scan state (warp A, lane<3 meaningful)
    float r = 0.f;

    for (int p = 0; p < ROUNDS; ++p) {
        // prefetch this warp's round-(p+1) pair
        float4 nx0 = z, nu0 = z, nx1 = z, nu1 = z;
        if (act && (p + 1 < ROUNDS)) {
            const int base = ((p + 1) * 4 + rowoff) * (DDIM / 4) + lane;
            nx0 = xr[base];              nu0 = ur[base];
            nx1 = xr[base + (DDIM / 4)]; nu1 = ur[base + (DDIM / 4)];
        }

        const int ma = (cu0.x < cx0.x) | ((cu0.y < cx0.y) << 1)
                     | ((cu0.z < cx0.z) << 2) | ((cu0.w < cx0.w) << 3);
        const int mb = (cu1.x < cx1.x) | ((cu1.y < cx1.y) << 1)
                     | ((cu1.z < cx1.z) << 2) | ((cu1.w < cx1.w) << 3);

        const int4 la = lut[(ma << 5) | lane];
        const int4 lb = lut[(mb << 5) | lane];
        const int sa0 = __reduce_add_sync(0xffffffffu, la.x);
        const int sb0 = __reduce_add_sync(0xffffffffu, lb.x);
        const int sa1 = __reduce_add_sync(0xffffffffu, la.y);
        const int sb1 = __reduce_add_sync(0xffffffffu, lb.y);
        const int sa2 = __reduce_add_sync(0xffffffffu, la.z);
        const int sb2 = __reduce_add_sync(0xffffffffu, lb.z);

        if (lane < OOUT) {
            const int va = (lane == 0) ? sa0 : ((lane == 1) ? sa1 : sa2);
            const int vb = (lane == 0) ? sb0 : ((lane == 1) ? sb1 : sb2);
            sums[pairid][p & 1][rowoff + 0][lane] = va;
            sums[pairid][p & 1][rowoff + 1][lane] = vb;
        }

        // per-batch-pair barrier (warps 2*pairid, 2*pairid+1; 64 threads)
        asm volatile("bar.sync %0, 64;" :: "r"(pairid + 1) : "memory");

        if (!isB && lane < OOUT) {
            #pragma unroll
            for (int k = 0; k < 4; ++k) {
                const float cur = (float)sums[pairid][p & 1][k][lane] * INV_FPSCALE + bl;
                m = beta * m + cur - r;
                const float sp = (m - thr > 0.f) ? 1.f : 0.f;
                r = sp * thr;
                const int t = 4 * p + k;
                const size_t o = (size_t)t * CW + (size_t)gw * OOUT + lane;
                __stcs(spk + o, sp);
                __stcs(mem + o, m);
            }
        }

        cx0 = nx0; cu0 = nu0; cx1 = nx1; cu1 = nu1;
    }
}

extern "C" void kernel_launch(void* const* d_in, const int* in_sizes, int n_in,
                              void* d_out, int out_size)
{
    const float* x    = (const float*)d_in[0];
    const float* u    = (const float*)d_in[1];
    const float* W    = (const float*)d_in[2];
    const float* bias = (const float*)d_in[3];
    const float* beta = (const float*)d_in[4];
    const float* thr  = (const float*)d_in[5];
    float* out = (float*)d_out;

    // 8192 warps = 2048 blocks of 128 threads (2 batches per block)
    leaky_fused<<<BATCH / 2, 128>>>(x, u, W, bias, beta, thr, out);
}